// round 13
// baseline (speedup 1.0000x reference)
#include <cuda_runtime.h>

#define NBATCH 64
#define NPTS   4096
#define NV4    32                  // 128 channels = 32 float4
#define NSL    32                  // slices per batch
#define PPS    (NPTS / NSL)        // 128 points per slice/CTA
#define PPWARP 16                  // points per warp (8 warps/CTA)

#define GB      32                 // batches per group-chain (64 MB of x)
#define NGROUPS (NBATCH / GB)      // 2

// scratch (device globals; no allocation)
__device__ float4 g_part [NBATCH * NSL * NV4];   // per-slice channel sums
__device__ float  g_vpart[NBATCH * NSL];         // per-slice sum of ||x_T||
__device__ int    g_cnt  [NBATCH];               // per-batch arrival counter

__device__ __forceinline__ float dot4(float4 a, float4 b) {
    return a.x * b.x + a.y * b.y + a.z * b.z + a.w * b.w;
}
__device__ __forceinline__ float warpsum(float v) {
    #pragma unroll
    for (int o = 16; o > 0; o >>= 1) v += __shfl_xor_sync(0xffffffffu, v, o);
    return v;
}
__device__ __forceinline__ void warpsum3(float& a, float& b, float& c) {
    #pragma unroll
    for (int o = 16; o > 0; o >>= 1) {
        a += __shfl_xor_sync(0xffffffffu, a, o);
        b += __shfl_xor_sync(0xffffffffu, b, o);
        c += __shfl_xor_sync(0xffffffffu, c, o);
    }
}

// ---------------- K0: zero arrival counters (graph-replay safe) ----------------
__global__ void k0_init() {
    g_cnt[threadIdx.x] = 0;
}

// ---------------- K1: per-slice channel sums ----------------
__global__ __launch_bounds__(256)
void k1_sums(const float* __restrict__ x, int b0) {
    const int b = b0 + (blockIdx.x >> 5), sl = blockIdx.x & 31;
    const int warp = threadIdx.x >> 5, lane = threadIdx.x & 31;
    const float4* __restrict__ xb = (const float4*)x + (size_t)b * NPTS * NV4;
    const int base = sl * PPS + warp * PPWARP;

    float4 acc = make_float4(0.f, 0.f, 0.f, 0.f);
    #pragma unroll 4
    for (int k = 0; k < PPWARP; ++k) {
        float4 v = xb[(size_t)(base + k) * NV4 + lane];
        acc.x += v.x; acc.y += v.y; acc.z += v.z; acc.w += v.w;
    }
    __shared__ float4 sr[256];
    sr[threadIdx.x] = acc;
    __syncthreads();
    #pragma unroll
    for (int off = 128; off >= 32; off >>= 1) {
        if (threadIdx.x < off) {
            float4 a = sr[threadIdx.x], c = sr[threadIdx.x + off];
            a.x += c.x; a.y += c.y; a.z += c.z; a.w += c.w;
            sr[threadIdx.x] = a;
        }
        __syncthreads();
    }
    if (threadIdx.x < 32) g_part[(b * NSL + sl) * NV4 + lane] = sr[lane];
}

// ---------------- K34: tangent + device barrier + expmap, fused ----------------
__global__ __launch_bounds__(256)
void k34_fused(const float* __restrict__ x, const float* __restrict__ beta,
               const float* __restrict__ gamma, float* __restrict__ out, int b0) {
    const int b = b0 + (blockIdx.x >> 5), sl = blockIdx.x & 31;
    const int tid = threadIdx.x, warp = tid >> 5, lane = tid & 31;
    const float4* __restrict__ xb = (const float4*)x + (size_t)b * NPTS * NV4;
    float4* __restrict__ ob       = (float4*)out + (size_t)b * NPTS * NV4;

    __shared__ float4 s_mean[32];
    __shared__ float  s_sc[12];
    __shared__ float  s_pt[8][PPWARP][5];   // per-point {s, s*alpha, c, dbt*i1b, sq}
    __shared__ float  s_nacc[8];

    const float4 beta4 = ((const float4*)beta)[lane];

    // --- warp 0: recompute mean + per-batch scalars from k1 partials (L2) ---
    if (warp == 0) {
        float4 m = make_float4(0.f, 0.f, 0.f, 0.f);
        #pragma unroll 4
        for (int s = 0; s < NSL; ++s) {
            float4 p = __ldcg(&g_part[(b * NSL + s) * NV4 + lane]);
            m.x += p.x; m.y += p.y; m.z += p.z; m.w += p.w;
        }
        const float invN = 1.0f / NPTS;
        m.x *= invN; m.y *= invN; m.z *= invN; m.w *= invN;

        float d     = warpsum(dot4(m, m));
        float m0raw = __shfl_sync(0xffffffffu, m.x, 0);
        float neg   = fmaxf(2.f * m0raw * m0raw - d, 1e-8f);   // -linner(m,m)
        float inv   = rsqrtf(neg);
        float4 mean = make_float4(m.x * inv, m.y * inv, m.z * inv, m.w * inv);
        s_mean[lane] = mean;

        float dmm = warpsum(dot4(mean, mean));
        float dbm = warpsum(dot4(beta4, mean));
        float dbb = warpsum(dot4(beta4, beta4));
        float mean0 = __shfl_sync(0xffffffffu, mean.x, 0);
        if (lane == 0) {
            float bb0 = beta4.x;
            float i1b = 1.f / (1.f + bb0);
            float nbb = dbb + 2.f * bb0 + 1.f;     // dot(beta+e0, beta+e0)
            float bp1 = bb0 + 1.f;
            s_sc[0] = mean0;
            s_sc[1] = 1.f / (1.f + mean0);
            s_sc[2] = dmm;
            s_sc[3] = dmm + 2.f * mean0 + 1.f;     // dot(mean+e0, mean+e0)
            s_sc[4] = dbm;
            s_sc[5] = dbm + bb0;                   // dot(beta, mean+e0)
            s_sc[6] = i1b;
            // K: linner(f,f) = g^2 * (t2 + dbt^2 * K)
            s_sc[7] = 2.f * i1b + i1b * i1b * (nbb - 2.f * bp1 * bp1);
        }
    }
    __syncthreads();

    const float4 mean4 = s_mean[lane];
    const float mean0 = s_sc[0], i1m = s_sc[1], dmm = s_sc[2], emem = s_sc[3];
    const float dbm   = s_sc[4], dbe = s_sc[5], i1b = s_sc[6], Kb = s_sc[7];

    float4 em = mean4, be = beta4;
    if (lane == 0) { em.x += 1.f; be.x += 1.f; }

    const int base = sl * PPS + warp * PPWARP;

    // ---------------- Phase 1: tangent scalars (x cached into L1) ----------
    float nacc = 0.f;
    #pragma unroll 2
    for (int k = 0; k < PPWARP; ++k) {
        float4 v = xb[(size_t)(base + k) * NV4 + lane];
        float dxx = dot4(v, v);
        float dxm = dot4(v, mean4);
        float dbx = dot4(v, beta4);
        warpsum3(dxx, dxm, dbx);
        float x0 = __shfl_sync(0xffffffffu, v.x, 0);

        float alpha = fmaxf(2.f * mean0 * x0 - dxm, 1.f + 1e-7f);
        float duu   = dxx - 2.f * alpha * dxm + alpha * alpha * dmm;  // dot(u,u)
        float u0    = x0 - alpha * mean0;
        float linuu = fmaxf(duu - 2.f * u0 * u0, 1e-8f);              // linner(u,u)
        float run   = rsqrtf(linuu);
        float ac    = __logf(alpha + sqrtf(fmaf(alpha, alpha, -1.f))); // acosh
        float s     = ac * run;
        float c     = s * u0 * i1m;
        float due   = dxm - alpha * dmm + u0;                         // dot(u, mean+e0)
        float t2    = fmaxf(s * s * duu - 2.f * s * c * due + c * c * emem, 0.f);
        float dbt   = s * (dbx - alpha * dbm) - c * dbe;              // dot(beta, x_T)
        float sq    = sqrtf(fmaxf(t2 + dbt * dbt * Kb, 0.f));
        nacc += sqrtf(t2);
        if (lane == 0) {   // scalars are warp-uniform; one lane stashes
            s_pt[warp][k][0] = s;
            s_pt[warp][k][1] = s * alpha;
            s_pt[warp][k][2] = c;
            s_pt[warp][k][3] = dbt * i1b;
            s_pt[warp][k][4] = sq;
        }
    }
    if (lane == 0) s_nacc[warp] = nacc;
    __syncthreads();

    // ---------------- Device-side per-batch barrier ------------------------
    if (tid == 0) {
        float t = 0.f;
        #pragma unroll
        for (int i = 0; i < 8; ++i) t += s_nacc[i];
        g_vpart[b * NSL + sl] = t;
        __threadfence();                       // partial visible before arrive
        atomicAdd(&g_cnt[b], 1);
        volatile int* cnt = &g_cnt[b];
        while (*cnt < NSL) __nanosleep(40);    // other warps park at barrier
    }
    __syncthreads();

    // deterministic var: every CTA sums the 32 partials in fixed order (L2)
    float vsum = 0.f;
    #pragma unroll 4
    for (int s = 0; s < NSL; ++s) vsum += __ldcg(&g_vpart[b * NSL + s]);
    const float var = vsum * (1.0f / NPTS);
    const float g   = gamma[0] / (var + 1e-5f);

    // ---------------- Phase 2: expmap + write (x re-read from L1) ----------
    #pragma unroll 4
    for (int k = 0; k < PPWARP; ++k) {
        const int p = base + k;
        float4 v = __ldcs(&xb[(size_t)p * NV4 + lane]);  // L1 hit, evict-first
        const float s   = s_pt[warp][k][0];
        const float sa  = s_pt[warp][k][1];
        const float c   = s_pt[warp][k][2];
        const float dbi = s_pt[warp][k][3];
        const float sq  = s_pt[warp][k][4];

        // y = g * x_T   (x_T0 = 0 exactly after transport to origin)
        float4 y;
        y.x = g * (s * v.x - sa * mean4.x - c * em.x);
        y.y = g * (s * v.y - sa * mean4.y - c * em.y);
        y.z = g * (s * v.z - sa * mean4.z - c * em.z);
        y.w = g * (s * v.w - sa * mean4.w - c * em.w);

        const float pt = g * dbi;              // linner(beta,y)/(1+b0)

        float4 f;
        f.x = y.x + pt * be.x;
        f.y = y.y + pt * be.y;
        f.z = y.z + pt * be.z;
        f.w = y.w + pt * be.w;

        // nu = sqrt(max(linner(f,f),1e-8)) = max(g*sq, 1e-4)
        const float nu  = fmaxf(g * sq, 1e-4f);
        const float ex  = __expf(nu);
        const float ei  = __expf(-nu);
        const float ch  = 0.5f * (ex + ei);
        const float sh  = 0.5f * (ex - ei) * __fdividef(1.f, nu);  // sinh/nu

        float4 o;
        o.x = ch * beta4.x + sh * f.x;
        o.y = ch * beta4.y + sh * f.y;
        o.z = ch * beta4.z + sh * f.z;
        o.w = ch * beta4.w + sh * f.w;
        __stcs(&ob[(size_t)p * NV4 + lane], o);  // streaming store
    }
}

extern "C" void kernel_launch(void* const* d_in, const int* in_sizes, int n_in,
                              void* d_out, int out_size) {
    const float* x     = (const float*)d_in[0];
    const float* beta  = (const float*)d_in[1];
    const float* gamma = (const float*)d_in[2];
    float* out = (float*)d_out;

    k0_init<<<1, NBATCH>>>();   // zero per-batch arrival counters each launch

    // Group chaining for L2 reuse: k1 warms L2 with the group's 64 MB of x;
    // k34 (fused tangent+barrier+expmap) re-reads it from L1/L2.
    for (int grp = 0; grp < NGROUPS; ++grp) {
        const int b0 = grp * GB;
        k1_sums  <<<GB * NSL, 256>>>(x, b0);
        k34_fused<<<GB * NSL, 256>>>(x, beta, gamma, out, b0);
    }
}

// round 15
// speedup vs baseline: 1.4878x; 1.4878x over previous
#include <cuda_runtime.h>

#define NBATCH 64
#define NPTS   4096
#define NV4    32                  // 128 channels = 32 float4
#define NSL    32                  // slices per batch
#define PPS    (NPTS / NSL)        // 128 points per slice/CTA
#define PPWARP 16                  // points per warp (8 warps/CTA)

#define GB      32                 // batches per group-chain (64 MB of x)
#define NGROUPS (NBATCH / GB)      // 2

// scratch (device globals; no allocation)
__device__ float4 g_part [NBATCH * NSL * NV4];
__device__ float4 g_mean [NBATCH * NV4];
__device__ float  g_sc   [NBATCH * 16];
__device__ float4 g_scr4 [NBATCH * NPTS];        // {s, s*alpha, c, dbt*i1b}
__device__ float  g_scrq [NBATCH * NPTS];        // sqrt(t2 + dbt^2 * K)
__device__ float  g_vpart[NBATCH * NSL];

__device__ __forceinline__ float dot4(float4 a, float4 b) {
    return a.x * b.x + a.y * b.y + a.z * b.z + a.w * b.w;
}
__device__ __forceinline__ float warpsum(float v) {
    #pragma unroll
    for (int o = 16; o > 0; o >>= 1) v += __shfl_xor_sync(0xffffffffu, v, o);
    return v;
}

// ---------------- K1: per-slice channel sums ----------------
__global__ __launch_bounds__(256)
void k1_sums(const float* __restrict__ x, int b0) {
    const int b = b0 + (blockIdx.x >> 5), sl = blockIdx.x & 31;
    const int warp = threadIdx.x >> 5, lane = threadIdx.x & 31;
    const float4* __restrict__ xb = (const float4*)x + (size_t)b * NPTS * NV4;
    const int base = sl * PPS + warp * PPWARP;

    float4 acc = make_float4(0.f, 0.f, 0.f, 0.f);
    #pragma unroll 4
    for (int k = 0; k < PPWARP; ++k) {
        float4 v = xb[(size_t)(base + k) * NV4 + lane];
        acc.x += v.x; acc.y += v.y; acc.z += v.z; acc.w += v.w;
    }
    __shared__ float4 sr[256];
    sr[threadIdx.x] = acc;
    __syncthreads();
    #pragma unroll
    for (int off = 128; off >= 32; off >>= 1) {
        if (threadIdx.x < off) {
            float4 a = sr[threadIdx.x], c = sr[threadIdx.x + off];
            a.x += c.x; a.y += c.y; a.z += c.z; a.w += c.w;
            sr[threadIdx.x] = a;
        }
        __syncthreads();
    }
    if (threadIdx.x < 32) g_part[(b * NSL + sl) * NV4 + lane] = sr[lane];
}

// ---------------- K2: mean + per-batch scalars ----------------
__global__ __launch_bounds__(32)
void k2_mean(const float* __restrict__ beta, int b0) {
    const int b = b0 + blockIdx.x, lane = threadIdx.x;
    const float4 beta4 = ((const float4*)beta)[lane];

    float4 m = make_float4(0.f, 0.f, 0.f, 0.f);
    for (int s = 0; s < NSL; ++s) {
        float4 p = g_part[(b * NSL + s) * NV4 + lane];
        m.x += p.x; m.y += p.y; m.z += p.z; m.w += p.w;
    }
    const float invN = 1.0f / NPTS;
    m.x *= invN; m.y *= invN; m.z *= invN; m.w *= invN;

    float d     = warpsum(dot4(m, m));
    float m0raw = __shfl_sync(0xffffffffu, m.x, 0);
    float neg   = fmaxf(2.f * m0raw * m0raw - d, 1e-8f);   // -linner(m,m)
    float inv   = rsqrtf(neg);
    float4 mean = make_float4(m.x * inv, m.y * inv, m.z * inv, m.w * inv);
    g_mean[b * NV4 + lane] = mean;

    float dmm = warpsum(dot4(mean, mean));
    float dbm = warpsum(dot4(beta4, mean));
    float dbb = warpsum(dot4(beta4, beta4));
    float mean0 = __shfl_sync(0xffffffffu, mean.x, 0);
    if (lane == 0) {
        float bb0 = beta4.x;
        float i1b = 1.f / (1.f + bb0);
        float nbb = dbb + 2.f * bb0 + 1.f;     // dot(beta+e0, beta+e0)
        float bp1 = bb0 + 1.f;
        float* sc = g_sc + b * 16;
        sc[0] = mean0;
        sc[1] = 1.f / (1.f + mean0);
        sc[2] = dmm;
        sc[3] = dmm + 2.f * mean0 + 1.f;   // dot(mean+e0, mean+e0)
        sc[4] = dbm;
        sc[5] = dbm + bb0;                 // dot(beta, mean+e0)
        sc[6] = bb0;
        sc[7] = i1b;
        sc[8] = nbb;
        // K: linner(f,f) = g^2 * (t2 + dbt^2 * K)
        sc[9] = 2.f * i1b + i1b * i1b * (nbb - 2.f * bp1 * bp1);
    }
}

// ---------------- K3: tangent scalars, 8-lane-per-point layout ----------------
__global__ __launch_bounds__(256)
void k3_tangent(const float* __restrict__ x, const float* __restrict__ beta, int b0) {
    const int b = b0 + (blockIdx.x >> 5), sl = blockIdx.x & 31;
    const int tid = threadIdx.x, warp = tid >> 5, lane = tid & 31;
    const int sub = lane & 7;                 // lane within 8-lane point-group
    const float4* __restrict__ xb = (const float4*)x + (size_t)b * NPTS * NV4;

    __shared__ float4 s_mean[32];
    __shared__ float4 s_beta[32];
    __shared__ float  s_nacc[8];

    if (tid < 32) {
        s_mean[tid] = g_mean[b * NV4 + tid];
        s_beta[tid] = ((const float4*)beta)[tid];
    }
    __syncthreads();

    const float* sc = g_sc + b * 16;
    const float mean0 = sc[0], i1m = sc[1], dmm = sc[2], emem = sc[3];
    const float dbm   = sc[4], dbe = sc[5], i1b = sc[7], Kb = sc[9];

    const int base = sl * PPS + warp * PPWARP;
    float nacc = 0.f;

    #pragma unroll
    for (int it = 0; it < PPWARP; it += 4) {
        const int p = base + it + (lane >> 3);          // group's point
        const float4* __restrict__ vp = xb + (size_t)p * NV4;

        float dxx = 0.f, dxm = 0.f, dbx = 0.f, x0loc = 0.f;
        #pragma unroll
        for (int i = 0; i < 4; ++i) {
            float4 v  = vp[sub + i * 8];
            if (i == 0 && sub == 0) x0loc = v.x;
            float4 mm = s_mean[sub + i * 8];
            float4 bb = s_beta[sub + i * 8];
            dxx += dot4(v, v);
            dxm += dot4(v, mm);
            dbx += dot4(v, bb);
        }
        // 3-round butterfly within each 8-lane group (independent across groups)
        #pragma unroll
        for (int o = 4; o > 0; o >>= 1) {
            dxx += __shfl_xor_sync(0xffffffffu, dxx, o);
            dxm += __shfl_xor_sync(0xffffffffu, dxm, o);
            dbx += __shfl_xor_sync(0xffffffffu, dbx, o);
        }
        const float x0 = __shfl_sync(0xffffffffu, x0loc, 0, 8);  // group broadcast

        float alpha = fmaxf(2.f * mean0 * x0 - dxm, 1.f + 1e-7f);
        float duu   = dxx - 2.f * alpha * dxm + alpha * alpha * dmm;  // dot(u,u)
        float u0    = x0 - alpha * mean0;
        float linuu = fmaxf(duu - 2.f * u0 * u0, 1e-8f);              // linner(u,u)
        float run   = rsqrtf(linuu);
        float ac    = __logf(alpha + sqrtf(fmaf(alpha, alpha, -1.f))); // acosh
        float s     = ac * run;
        float c     = s * u0 * i1m;
        float due   = dxm - alpha * dmm + u0;                         // dot(u, mean+e0)
        float t2    = fmaxf(s * s * duu - 2.f * s * c * due + c * c * emem, 0.f);
        float dbt   = s * (dbx - alpha * dbm) - c * dbe;              // dot(beta, x_T)
        float sq    = sqrtf(fmaxf(t2 + dbt * dbt * Kb, 0.f));
        nacc += sqrtf(t2);
        if (sub == 0) {
            const size_t o = (size_t)b * NPTS + p;
            g_scr4[o] = make_float4(s, s * alpha, c, dbt * i1b);
            g_scrq[o] = sq;
        }
    }

    // each point counted once: take sub==0 lane of each group
    float contrib = (sub == 0) ? nacc : 0.f;
    contrib = warpsum(contrib);
    if (lane == 0) s_nacc[warp] = contrib;
    __syncthreads();
    if (tid == 0) {
        float t = 0.f;
        #pragma unroll
        for (int i = 0; i < 8; ++i) t += s_nacc[i];
        g_vpart[b * NSL + sl] = t;
    }
}

// ---------------- K4: scale, transport to beta, expmap, write ----------------
__global__ __launch_bounds__(256)
void k4_final(const float* __restrict__ x, const float* __restrict__ beta,
              const float* __restrict__ gamma, float* __restrict__ out, int b0) {
    const int b = b0 + (blockIdx.x >> 5), sl = blockIdx.x & 31;
    const int warp = threadIdx.x >> 5, lane = threadIdx.x & 31;
    const float4* __restrict__ xb = (const float4*)x + (size_t)b * NPTS * NV4;
    float4* __restrict__ ob       = (float4*)out + (size_t)b * NPTS * NV4;

    float vsum = 0.f;
    #pragma unroll
    for (int s = 0; s < NSL; ++s) vsum += g_vpart[b * NSL + s];
    const float var = vsum * (1.0f / NPTS);
    const float g   = gamma[0] / (var + 1e-5f);

    const float4 mean4 = g_mean[b * NV4 + lane];
    const float4 beta4 = ((const float4*)beta)[lane];

    float4 em = mean4, be = beta4;
    if (lane == 0) { em.x += 1.f; be.x += 1.f; }

    const int base = sl * PPS + warp * PPWARP;
    #pragma unroll 4
    for (int k = 0; k < PPWARP; ++k) {
        const int p = base + k;
        float4 v  = __ldcs(&xb[(size_t)p * NV4 + lane]);   // last use of x: evict-first
        float4 A  = g_scr4[(size_t)b * NPTS + p];          // uniform broadcast load
        float  sq = g_scrq[(size_t)b * NPTS + p];
        const float s = A.x, sa = A.y, c = A.z, dbi = A.w; // dbi = dbt * i1b

        // y = g * x_T  (x_T0 = 0 exactly after transport to origin)
        float4 y;
        y.x = g * (s * v.x - sa * mean4.x - c * em.x);
        y.y = g * (s * v.y - sa * mean4.y - c * em.y);
        y.z = g * (s * v.z - sa * mean4.z - c * em.z);
        y.w = g * (s * v.w - sa * mean4.w - c * em.w);

        const float pt = g * dbi;              // linner(beta,y)/(1+b0)

        float4 f;
        f.x = y.x + pt * be.x;
        f.y = y.y + pt * be.y;
        f.z = y.z + pt * be.z;
        f.w = y.w + pt * be.w;

        // nu = sqrt(max(linner(f,f),1e-8)) = max(g*sq, 1e-4)
        const float nu  = fmaxf(g * sq, 1e-4f);
        const float ex  = __expf(nu);
        const float ei  = __expf(-nu);
        const float ch  = 0.5f * (ex + ei);
        const float sh  = 0.5f * (ex - ei) * __fdividef(1.f, nu);  // sinh(nu)/nu

        float4 o;
        o.x = ch * beta4.x + sh * f.x;
        o.y = ch * beta4.y + sh * f.y;
        o.z = ch * beta4.z + sh * f.z;
        o.w = ch * beta4.w + sh * f.w;
        __stcs(&ob[(size_t)p * NV4 + lane], o);  // streaming store
    }
}

extern "C" void kernel_launch(void* const* d_in, const int* in_sizes, int n_in,
                              void* d_out, int out_size) {
    const float* x     = (const float*)d_in[0];
    const float* beta  = (const float*)d_in[1];
    const float* gamma = (const float*)d_in[2];
    float* out = (float*)d_out;

    // Single-stream group chaining: each group of GB batches (64 MB of x)
    // runs k1->k2->k3->k4 back-to-back so k3/k4 re-read the group's x from L2.
    for (int grp = 0; grp < NGROUPS; ++grp) {
        const int b0 = grp * GB;
        k1_sums   <<<GB * NSL, 256>>>(x, b0);
        k2_mean   <<<GB,       32 >>>(beta, b0);
        k3_tangent<<<GB * NSL, 256>>>(x, beta, b0);
        k4_final  <<<GB * NSL, 256>>>(x, beta, gamma, out, b0);
    }
}